// round 3
// baseline (speedup 1.0000x reference)
#include <cuda_runtime.h>
#include <math.h>

// ChannelDropout:
//   kept[b,c]  = ||positions[b,c] - center|| > 0.2
//   proba[b,c] = mean_i( ||positions[b,c] - mc_centers[i]|| > 0.2 )
//   out[b,c,t] = brain_sig[b,c,t] * kept / (1e-8 + proba)
//
// One block per (b,c) row. Scale computed cooperatively (threads 0..n_mc-1),
// broadcast via shared memory; row data streamed as float4.

#define DROPOUT_R 0.2f
#define EPS_V     1e-8f

__device__ __forceinline__ bool dist_gt(float px, float py, float qx, float qy) {
    // Match jnp.linalg.norm(...) > 0.2 bit-for-bit: unfused mul/add + exact sqrt.
    float dx = px - qx;
    float dy = py - qy;
    float d2 = __fadd_rn(__fmul_rn(dx, dx), __fmul_rn(dy, dy));
    return sqrtf(d2) > DROPOUT_R;
}

__global__ void __launch_bounds__(256)
channel_dropout_kernel(const float* __restrict__ sig,
                       const float* __restrict__ pos,
                       const float* __restrict__ center,
                       const float* __restrict__ mc,
                       float* __restrict__ out,
                       int T, int n_mc)
{
    const int row = blockIdx.x;
    const int tid = threadIdx.x;

    __shared__ int   s_cnt;
    __shared__ float s_scale;
    if (tid == 0) s_cnt = 0;

    const float px = __ldg(&pos[2 * row]);
    const float py = __ldg(&pos[2 * row + 1]);

    const int T4 = T >> 2;                       // float4 count (T=3000 -> 750)
    const float4* __restrict__ src = reinterpret_cast<const float4*>(sig) + (size_t)row * T4;
    float4*       __restrict__ dst = reinterpret_cast<float4*>(out)       + (size_t)row * T4;

    // Front-batch the row loads so HBM traffic is in flight while the
    // (cheap) scale computation runs.
    const int i0 = tid;
    const int i1 = tid + 256;
    const int i2 = tid + 512;
    const bool p0 = i0 < T4, p1 = i1 < T4, p2 = i2 < T4;
    float4 v0, v1, v2;
    if (p0) v0 = src[i0];
    if (p1) v1 = src[i1];
    if (p2) v2 = src[i2];

    __syncthreads();                              // s_cnt = 0 visible

    // Monte-Carlo keep-probability: distribute the n_mc (=100) tests.
    int local = 0;
    for (int i = tid; i < n_mc; i += 256) {
        float mx = __ldg(&mc[2 * i]);
        float my = __ldg(&mc[2 * i + 1]);
        if (dist_gt(px, py, mx, my)) local++;
    }
    if (local) atomicAdd(&s_cnt, local);
    __syncthreads();

    if (tid == 0) {
        bool kept = dist_gt(px, py, __ldg(&center[0]), __ldg(&center[1]));
        float proba = (float)s_cnt / (float)n_mc;
        s_scale = kept ? (1.0f / (EPS_V + proba)) : 0.0f;
    }
    __syncthreads();

    const float sc = s_scale;

    if (p0) { v0.x *= sc; v0.y *= sc; v0.z *= sc; v0.w *= sc; dst[i0] = v0; }
    if (p1) { v1.x *= sc; v1.y *= sc; v1.z *= sc; v1.w *= sc; dst[i1] = v1; }
    if (p2) { v2.x *= sc; v2.y *= sc; v2.z *= sc; v2.w *= sc; dst[i2] = v2; }

    // Generic continuation if T4 > 768 (not hit for T=3000).
    for (int i = tid + 768; i < T4; i += 256) {
        float4 v = src[i];
        v.x *= sc; v.y *= sc; v.z *= sc; v.w *= sc;
        dst[i] = v;
    }

    // Scalar tail if T not divisible by 4 (not hit for T=3000).
    const int tail = T4 << 2;
    const float* srow = sig + (size_t)row * T;
    float*       drow = out + (size_t)row * T;
    for (int t = tail + tid; t < T; t += 256) {
        drow[t] = srow[t] * sc;
    }
}

extern "C" void kernel_launch(void* const* d_in, const int* in_sizes, int n_in,
                              void* d_out, int out_size)
{
    const float* sig    = (const float*)d_in[0];   // brain_sig  (B*C*T)
    const float* pos    = (const float*)d_in[1];   // positions  (B*C*2)
    const float* center = (const float*)d_in[2];   // center     (2)
    const float* mc     = (const float*)d_in[3];   // mc_centers (N*2)
    float*       out    = (float*)d_out;

    const int rows = in_sizes[1] / 2;              // B*C = 17472
    const int T    = in_sizes[0] / rows;           // 3000
    const int n_mc = in_sizes[3] / 2;              // 100

    channel_dropout_kernel<<<rows, 256>>>(sig, pos, center, mc, out, T, n_mc);
}

// round 4
// speedup vs baseline: 1.0005x; 1.0005x over previous
#include <cuda_runtime.h>
#include <math.h>

// ChannelDropout, warp-autonomous version:
//   kept[b,c]  = ||positions[b,c] - center|| > 0.2
//   proba[b,c] = mean_i( ||positions[b,c] - mc_centers[i]|| > 0.2 )
//   out[b,c,t] = brain_sig[b,c,t] * kept / (1e-8 + proba)
//
// One block per (b,c) row. Each WARP redundantly computes the row scale
// (100 MC tests split 32-wide + __reduce_add_sync) so there are NO block
// barriers, NO shared memory, NO atomics: each warp's stores issue as soon
// as its own loads land. ALU/FMA pipes were <15% busy, so the 8x redundant
// scale compute is free; removing BAR.SYNC removes the per-block bubble
// between the load wave and the store wave.

#define DROPOUT_R 0.2f
#define EPS_V     1e-8f

__device__ __forceinline__ bool dist_gt(float px, float py, float qx, float qy) {
    // Match jnp.linalg.norm(...) > 0.2 bit-for-bit: unfused mul/add + exact sqrt.
    float dx = px - qx;
    float dy = py - qy;
    float d2 = __fadd_rn(__fmul_rn(dx, dx), __fmul_rn(dy, dy));
    return sqrtf(d2) > DROPOUT_R;
}

__global__ void __launch_bounds__(256)
channel_dropout_kernel(const float* __restrict__ sig,
                       const float* __restrict__ pos,
                       const float* __restrict__ center,
                       const float* __restrict__ mc,
                       float* __restrict__ out,
                       int T, int n_mc)
{
    const int row  = blockIdx.x;
    const int tid  = threadIdx.x;
    const int lane = tid & 31;

    const int T4 = T >> 2;                       // float4 count (T=3000 -> 750)
    const float4* __restrict__ src = reinterpret_cast<const float4*>(sig) + (size_t)row * T4;
    float4*       __restrict__ dst = reinterpret_cast<float4*>(out)       + (size_t)row * T4;

    // Front-batch the row loads so the HBM stream is in flight while the
    // (cheap) per-warp scale computation runs. Streaming hint: data is
    // touched exactly once and exceeds L2 capacity.
    const int i0 = tid;
    const int i1 = tid + 256;
    const int i2 = tid + 512;
    const bool p0 = i0 < T4, p1 = i1 < T4, p2 = i2 < T4;
    float4 v0, v1, v2;
    if (p0) v0 = __ldcs(&src[i0]);
    if (p1) v1 = __ldcs(&src[i1]);
    if (p2) v2 = __ldcs(&src[i2]);

    // Per-warp Monte-Carlo keep-probability (redundant across the 8 warps of
    // the block -- cheaper than a barrier). All lanes read the same pos pair
    // (L1 broadcast); mc centers read as float2 (800 B, L1-resident).
    const float2 p = __ldg(reinterpret_cast<const float2*>(pos) + row);
    const float2* __restrict__ mc2 = reinterpret_cast<const float2*>(mc);

    int local = 0;
    for (int i = lane; i < n_mc; i += 32) {
        float2 c = __ldg(&mc2[i]);
        if (dist_gt(p.x, p.y, c.x, c.y)) local++;
    }
    const int cnt = __reduce_add_sync(0xffffffffu, local);

    const bool  kept  = dist_gt(p.x, p.y, __ldg(&center[0]), __ldg(&center[1]));
    const float proba = (float)cnt / (float)n_mc;
    const float sc    = kept ? (1.0f / (EPS_V + proba)) : 0.0f;

    if (p0) { v0.x *= sc; v0.y *= sc; v0.z *= sc; v0.w *= sc; __stcs(&dst[i0], v0); }
    if (p1) { v1.x *= sc; v1.y *= sc; v1.z *= sc; v1.w *= sc; __stcs(&dst[i1], v1); }
    if (p2) { v2.x *= sc; v2.y *= sc; v2.z *= sc; v2.w *= sc; __stcs(&dst[i2], v2); }

    // Generic continuation if T4 > 768 (not hit for T=3000).
    for (int i = tid + 768; i < T4; i += 256) {
        float4 v = __ldcs(&src[i]);
        v.x *= sc; v.y *= sc; v.z *= sc; v.w *= sc;
        __stcs(&dst[i], v);
    }

    // Scalar tail if T not divisible by 4 (not hit for T=3000).
    const int tail = T4 << 2;
    const float* srow = sig + (size_t)row * T;
    float*       drow = out + (size_t)row * T;
    for (int t = tail + tid; t < T; t += 256) {
        drow[t] = srow[t] * sc;
    }
}

extern "C" void kernel_launch(void* const* d_in, const int* in_sizes, int n_in,
                              void* d_out, int out_size)
{
    const float* sig    = (const float*)d_in[0];   // brain_sig  (B*C*T)
    const float* pos    = (const float*)d_in[1];   // positions  (B*C*2)
    const float* center = (const float*)d_in[2];   // center     (2)
    const float* mc     = (const float*)d_in[3];   // mc_centers (N*2)
    float*       out    = (float*)d_out;

    const int rows = in_sizes[1] / 2;              // B*C = 17472
    const int T    = in_sizes[0] / rows;           // 3000
    const int n_mc = in_sizes[3] / 2;              // 100

    channel_dropout_kernel<<<rows, 256>>>(sig, pos, center, mc, out, T, n_mc);
}